// round 12
// baseline (speedup 1.0000x reference)
#include <cuda_runtime.h>

// 2-layer LSTM (IN=16, H=32, T=512, B=4096) + MLP head, fully fused.
// R12: GATE-SPLIT quads. 4 warps share 8 sequences:
//   role 0 = L0 gates (i,f) | role 1 = L0 gates (g,o)
//   role 2 = L1 gates (i,f) | role 3 = L1 gates (g,o)
// Each warp loads only its 2 gates' weight quads -> total weight-LDS delivery
// unchanged vs R9/R11 while warps/SM doubles to 16 (4/SMSP) for latency
// hiding. quad = warp&3 puts a full quad on one SMSP (FMA balanced at 3584
// cyc/SMSP-step). Gate halves exchanged through smem u64 + 64-thread named
// bar; cells split 4 seqs/warp. L1 lags one timestep; one 128-thread named
// bar per iteration publishes h0/h1/x. Activations sigmoid/tanh use HW
// tanh.approx.f32 (MUFU halved, shorter cell tail).

#define FULLMASK 0xffffffffu
typedef unsigned long long u64;

constexpr int T_LEN = 512;
constexpr int IN_DIM = 16;
constexpr int H_DIM = 32;
constexpr int SEQ_PER_QUAD = 8;
constexpr int QUADS = 4;            // per block
constexpr int THREADS = 512;        // 16 warps

// Weights as j-pair gate quads: A=(wi[j0],wi[j1],wf[j0],wf[j1]), B=(wg..,wo..)
struct SmemW {
    float4 ihA0[IN_DIM / 2][H_DIM];
    float4 ihB0[IN_DIM / 2][H_DIM];
    float4 hhA0[H_DIM / 2][H_DIM];
    float4 hhB0[H_DIM / 2][H_DIM];
    float4 ihA1[H_DIM / 2][H_DIM];
    float4 ihB1[H_DIM / 2][H_DIM];
    float4 hhA1[H_DIM / 2][H_DIM];
    float4 hhB1[H_DIM / 2][H_DIM];
    float4 bg0[H_DIM];
    float4 bg1[H_DIM];
};

// Per-quad staging. h(t) lives in slot (t+1)&1; x(t) in slot t&1.
struct __align__(16) Stage {
    float h0[2][SEQ_PER_QUAD][H_DIM];
    float h1[2][SEQ_PER_QUAD][H_DIM];
    float x[2][SEQ_PER_QUAD][IN_DIM];
    u64 exGO0[4][H_DIM];   // L0-GO -> (g,o) of seqs 0-3, read by L0-IF
    u64 exIF0[4][H_DIM];   // L0-IF -> (i,f) of seqs 4-7, read by L0-GO
    u64 exGO1[4][H_DIM];   // L1 likewise
    u64 exIF1[4][H_DIM];
};

struct SmemAll {
    SmemW w;
    Stage st[QUADS];
};

__device__ __forceinline__ u64 fma2(u64 a, u64 b, u64 c) {
    u64 d;
    asm("fma.rn.f32x2 %0, %1, %2, %3;" : "=l"(d) : "l"(a), "l"(b), "l"(c));
    return d;
}
__device__ __forceinline__ u64 pack2f(float a, float b) {
    u64 r;
    asm("mov.b64 %0, {%1, %2};" : "=l"(r) : "f"(a), "f"(b));
    return r;
}
__device__ __forceinline__ float2 unpack2(u64 v) {
    float2 r;
    asm("mov.b64 {%0, %1}, %2;" : "=f"(r.x), "=f"(r.y) : "l"(v));
    return r;
}
__device__ __forceinline__ float hsum2(u64 v) {
    float2 r = unpack2(v);
    return r.x + r.y;
}
__device__ __forceinline__ float tanh_ap(float v) {
    float r;
    asm("tanh.approx.f32 %0, %1;" : "=f"(r) : "f"(v));
    return r;
}
__device__ __forceinline__ float sig_ap(float v) {
    return fmaf(tanh_ap(v * 0.5f), 0.5f, 0.5f);
}

__device__ __forceinline__ void bar_named(int id, int cnt) {
    asm volatile("bar.sync %0, %1;" :: "r"(id), "r"(cnt) : "memory");
}

// 2-gate accumulation over one 2-jp group (dims 4g..4g+3).
#define GRP2(W, g, ACTP, FIRST)                                               \
    do {                                                                      \
        ulonglong2 w0 = *reinterpret_cast<const ulonglong2*>(&W[2*(g)][lane]);   \
        ulonglong2 w1 = *reinterpret_cast<const ulonglong2*>(&W[2*(g)+1][lane]); \
        _Pragma("unroll")                                                     \
        for (int ss = 0; ss < 8; ss++) {                                      \
            ulonglong2 a = *reinterpret_cast<const ulonglong2*>(ACTP(ss));    \
            if (FIRST) {                                                      \
                aA[ss] = fma2(w0.x, a.x, BA);                                 \
                aB[ss] = fma2(w0.y, a.x, BB);                                 \
            } else {                                                          \
                aA[ss] = fma2(w0.x, a.x, aA[ss]);                             \
                aB[ss] = fma2(w0.y, a.x, aB[ss]);                             \
            }                                                                 \
            aA[ss] = fma2(w1.x, a.y, aA[ss]);                                 \
            aB[ss] = fma2(w1.y, a.y, aB[ss]);                                 \
        }                                                                     \
    } while (0)

__global__ void __launch_bounds__(THREADS, 1)
lstm_fused_kernel(const float* __restrict__ x,
                  const float* __restrict__ Wih0, const float* __restrict__ Whh0,
                  const float* __restrict__ bih0, const float* __restrict__ bhh0,
                  const float* __restrict__ Wih1, const float* __restrict__ Whh1,
                  const float* __restrict__ bih1, const float* __restrict__ bhh1,
                  const float* __restrict__ W1, const float* __restrict__ b1,
                  const float* __restrict__ W2, const float* __restrict__ b2,
                  float* __restrict__ out, int batch) {
    extern __shared__ char smem_raw[];
    SmemAll* sm = reinterpret_cast<SmemAll*>(smem_raw);
    SmemW* s = &sm->w;

    const int tid = threadIdx.x;
    if (blockIdx.x * (QUADS * SEQ_PER_QUAD) >= batch) return;  // block-uniform

    // ---- Stage weights as j-pair gate quads ----
    for (int i = tid; i < (IN_DIM / 2) * H_DIM; i += THREADS) {
        int jp = i / H_DIM, u = i % H_DIM;
        int j0 = 2 * jp, j1 = 2 * jp + 1;
        s->ihA0[jp][u] = make_float4(Wih0[(0 * H_DIM + u) * IN_DIM + j0],
                                     Wih0[(0 * H_DIM + u) * IN_DIM + j1],
                                     Wih0[(1 * H_DIM + u) * IN_DIM + j0],
                                     Wih0[(1 * H_DIM + u) * IN_DIM + j1]);
        s->ihB0[jp][u] = make_float4(Wih0[(2 * H_DIM + u) * IN_DIM + j0],
                                     Wih0[(2 * H_DIM + u) * IN_DIM + j1],
                                     Wih0[(3 * H_DIM + u) * IN_DIM + j0],
                                     Wih0[(3 * H_DIM + u) * IN_DIM + j1]);
    }
    for (int i = tid; i < (H_DIM / 2) * H_DIM; i += THREADS) {
        int jp = i / H_DIM, u = i % H_DIM;
        int j0 = 2 * jp, j1 = 2 * jp + 1;
        s->hhA0[jp][u] = make_float4(Whh0[(0 * H_DIM + u) * H_DIM + j0],
                                     Whh0[(0 * H_DIM + u) * H_DIM + j1],
                                     Whh0[(1 * H_DIM + u) * H_DIM + j0],
                                     Whh0[(1 * H_DIM + u) * H_DIM + j1]);
        s->hhB0[jp][u] = make_float4(Whh0[(2 * H_DIM + u) * H_DIM + j0],
                                     Whh0[(2 * H_DIM + u) * H_DIM + j1],
                                     Whh0[(3 * H_DIM + u) * H_DIM + j0],
                                     Whh0[(3 * H_DIM + u) * H_DIM + j1]);
        s->ihA1[jp][u] = make_float4(Wih1[(0 * H_DIM + u) * H_DIM + j0],
                                     Wih1[(0 * H_DIM + u) * H_DIM + j1],
                                     Wih1[(1 * H_DIM + u) * H_DIM + j0],
                                     Wih1[(1 * H_DIM + u) * H_DIM + j1]);
        s->ihB1[jp][u] = make_float4(Wih1[(2 * H_DIM + u) * H_DIM + j0],
                                     Wih1[(2 * H_DIM + u) * H_DIM + j1],
                                     Wih1[(3 * H_DIM + u) * H_DIM + j0],
                                     Wih1[(3 * H_DIM + u) * H_DIM + j1]);
        s->hhA1[jp][u] = make_float4(Whh1[(0 * H_DIM + u) * H_DIM + j0],
                                     Whh1[(0 * H_DIM + u) * H_DIM + j1],
                                     Whh1[(1 * H_DIM + u) * H_DIM + j0],
                                     Whh1[(1 * H_DIM + u) * H_DIM + j1]);
        s->hhB1[jp][u] = make_float4(Whh1[(2 * H_DIM + u) * H_DIM + j0],
                                     Whh1[(2 * H_DIM + u) * H_DIM + j1],
                                     Whh1[(3 * H_DIM + u) * H_DIM + j0],
                                     Whh1[(3 * H_DIM + u) * H_DIM + j1]);
    }
    for (int u = tid; u < H_DIM; u += THREADS) {
        s->bg0[u] = make_float4(bih0[0 * H_DIM + u] + bhh0[0 * H_DIM + u],
                                bih0[1 * H_DIM + u] + bhh0[1 * H_DIM + u],
                                bih0[2 * H_DIM + u] + bhh0[2 * H_DIM + u],
                                bih0[3 * H_DIM + u] + bhh0[3 * H_DIM + u]);
        s->bg1[u] = make_float4(bih1[0 * H_DIM + u] + bhh1[0 * H_DIM + u],
                                bih1[1 * H_DIM + u] + bhh1[1 * H_DIM + u],
                                bih1[2 * H_DIM + u] + bhh1[2 * H_DIM + u],
                                bih1[3 * H_DIM + u] + bhh1[3 * H_DIM + u]);
    }

    const int warp = tid >> 5;
    const int lane = tid & 31;     // lane = hidden unit
    const int quad = warp & 3;     // one quad per SMSP
    const int role = warp >> 2;    // 0:L0IF 1:L0GO 2:L1IF 3:L1GO
    Stage* st = &sm->st[quad];
    const int seq_base = (blockIdx.x * QUADS + quad) * SEQ_PER_QUAD;

    const int BAR_L0 = 1 + quad;      // 64-thread: roles 0,1
    const int BAR_L1 = 5 + quad;      // 64-thread: roles 2,3
    const int BAR_Q  = 9 + quad;      // 128-thread: all roles

    const int xs = lane >> 2, xq = lane & 3;
    const size_t seq_stride = (size_t)T_LEN * IN_DIM;
    const float* xload = x + (size_t)(seq_base + xs) * seq_stride + 4 * xq;

    // ---- Init staging ----
    if (role == 0) {
#pragma unroll
        for (int ss = 0; ss < 8; ss++) st->h0[0][ss][lane] = 0.f;  // h0(-1)
        *reinterpret_cast<float4*>(&st->x[0][xs][4 * xq]) =
            *reinterpret_cast<const float4*>(xload);               // x(0)
    } else if (role == 2) {
#pragma unroll
        for (int ss = 0; ss < 8; ss++) st->h1[0][ss][lane] = 0.f;  // h1(-1)
    }
    __syncthreads();

    const bool isL1 = role >= 2;
    const bool isGO = role & 1;
    const float4 bv = isL1 ? s->bg1[lane] : s->bg0[lane];
    // IF: gates (i,f); GO: gates (g,o). Split-half accum (lo even j, hi odd).
    const u64 BA = pack2f(isGO ? bv.z : bv.x, 0.f);
    const u64 BB = pack2f(isGO ? bv.w : bv.y, 0.f);

    float c[4] = {0.f, 0.f, 0.f, 0.f};   // owned seqs: IF 0-3, GO 4-7
    const int own = isGO ? 4 : 0;

    if (!isL1) {
        // ===================== Layer-0 warps =====================
        for (int k = 0; k < T_LEN; k++) {
            const int xbuf = k & 1;          // x(k)
            const int hrd = k & 1;           // h0(k-1)
            const int hwr = hrd ^ 1;         // h0(k)

            float4 xn = make_float4(0.f, 0.f, 0.f, 0.f);
            if (role == 0 && k + 1 < T_LEN)
                xn = *reinterpret_cast<const float4*>(xload + (k + 1) * IN_DIM);

            u64 aA[8], aB[8];
            if (!isGO) {
#pragma unroll
                for (int g = 0; g < IN_DIM / 4; g++) {
#define AX(ss) (&st->x[xbuf][ss][4 * g])
                    GRP2(s->ihA0, g, AX, (g == 0));
#undef AX
                }
#pragma unroll
                for (int g = 0; g < H_DIM / 4; g++) {
#define AH(ss) (&st->h0[hrd][ss][4 * g])
                    GRP2(s->hhA0, g, AH, false);
#undef AH
                }
            } else {
#pragma unroll
                for (int g = 0; g < IN_DIM / 4; g++) {
#define AX(ss) (&st->x[xbuf][ss][4 * g])
                    GRP2(s->ihB0, g, AX, (g == 0));
#undef AX
                }
#pragma unroll
                for (int g = 0; g < H_DIM / 4; g++) {
#define AH(ss) (&st->h0[hrd][ss][4 * g])
                    GRP2(s->hhB0, g, AH, false);
#undef AH
                }
            }
            // Export partner seqs' gate pair
#pragma unroll
            for (int p = 0; p < 4; p++) {
                int ss = (own ^ 4) + p;   // the 4 seqs the partner owns
                u64 v = pack2f(hsum2(aA[ss]), hsum2(aB[ss]));
                if (!isGO) st->exIF0[p][lane] = v;
                else       st->exGO0[p][lane] = v;
            }
            bar_named(BAR_L0, 64);
            // Cells for own seqs
#pragma unroll
            for (int p = 0; p < 4; p++) {
                int ss = own + p;
                float2 other = unpack2(isGO ? st->exIF0[p][lane]
                                            : st->exGO0[p][lane]);
                float gi, gf, gg, go_;
                if (!isGO) { gi = hsum2(aA[ss]); gf = hsum2(aB[ss]);
                             gg = other.x;       go_ = other.y; }
                else       { gi = other.x;       gf = other.y;
                             gg = hsum2(aA[ss]); go_ = hsum2(aB[ss]); }
                float iv = sig_ap(gi), fv = sig_ap(gf);
                float gv = tanh_ap(gg), ov = sig_ap(go_);
                c[p] = fmaf(fv, c[p], iv * gv);
                st->h0[hwr][ss][lane] = ov * tanh_ap(c[p]);
            }
            if (role == 0)
                *reinterpret_cast<float4*>(&st->x[xbuf ^ 1][xs][4 * xq]) = xn;
            bar_named(BAR_Q, 128);   // publish h0(k), x(k+1); sync with L1
        }
        return;
    }

    // ===================== Layer-1 warps (lag 1 step) =====================
    float hfin[4];  // final h per owned seq (registers; also staged)
    for (int k = 0; k <= T_LEN; k++) {
        if (k >= 1) {
            const int t = k - 1;
            const int h1rd = (k - 1) & 1;   // h1(t-1) slot par(k-1)
            const int h0rd = k & 1;         // h0(t)   slot par(k)
            const int h1wr = k & 1;         // h1(t)   slot par(k)... (==h0rd)

            u64 aA[8], aB[8];
            if (!isGO) {
#pragma unroll
                for (int g = 0; g < H_DIM / 4; g++) {
#define AH1(ss) (&st->h1[h1rd][ss][4 * g])
                    GRP2(s->hhA1, g, AH1, (g == 0));
#undef AH1
                }
#pragma unroll
                for (int g = 0; g < H_DIM / 4; g++) {
#define AH0(ss) (&st->h0[h0rd][ss][4 * g])
                    GRP2(s->ihA1, g, AH0, false);
#undef AH0
                }
            } else {
#pragma unroll
                for (int g = 0; g < H_DIM / 4; g++) {
#define AH1(ss) (&st->h1[h1rd][ss][4 * g])
                    GRP2(s->hhB1, g, AH1, (g == 0));
#undef AH1
                }
#pragma unroll
                for (int g = 0; g < H_DIM / 4; g++) {
#define AH0(ss) (&st->h0[h0rd][ss][4 * g])
                    GRP2(s->ihB1, g, AH0, false);
#undef AH0
                }
            }
#pragma unroll
            for (int p = 0; p < 4; p++) {
                int ss = (own ^ 4) + p;
                u64 v = pack2f(hsum2(aA[ss]), hsum2(aB[ss]));
                if (!isGO) st->exIF1[p][lane] = v;
                else       st->exGO1[p][lane] = v;
            }
            bar_named(BAR_L1, 64);
#pragma unroll
            for (int p = 0; p < 4; p++) {
                int ss = own + p;
                float2 other = unpack2(isGO ? st->exIF1[p][lane]
                                            : st->exGO1[p][lane]);
                float gi, gf, gg, go_;
                if (!isGO) { gi = hsum2(aA[ss]); gf = hsum2(aB[ss]);
                             gg = other.x;       go_ = other.y; }
                else       { gi = other.x;       gf = other.y;
                             gg = hsum2(aA[ss]); go_ = hsum2(aB[ss]); }
                float iv = sig_ap(gi), fv = sig_ap(gf);
                float gv = tanh_ap(gg), ov = sig_ap(go_);
                c[p] = fmaf(fv, c[p], iv * gv);
                float h = ov * tanh_ap(c[p]);
                hfin[p] = h;
                st->h1[h1wr][ss][lane] = h;
            }
            (void)hfin;
        }
        if (k < T_LEN) bar_named(BAR_Q, 128);  // L0 still running
        else bar_named(BAR_L1, 64);            // final h1 stores visible in pair
    }

    // ---- Head (L1 warps, 4 owned seqs each) ----
    // h1(T-1) staged in slot T_LEN & 1 == 0.
    const int hslot = T_LEN & 1;
    float bias2 = __ldg(b2);
    float bm = (lane < 16) ? __ldg(b1 + lane) : 0.f;
    float w2m = (lane < 16) ? __ldg(W2 + lane) : 0.f;
#pragma unroll
    for (int p = 0; p < 4; p++) {
        int ss = own + p;
        float z = bm;
#pragma unroll
        for (int j = 0; j < H_DIM; j++) {
            float wm = (lane < 16) ? __ldg(W1 + lane * H_DIM + j) : 0.f;
            z = fmaf(wm, st->h1[hslot][ss][j], z);
        }
        float v = fmaxf(z, 0.f) * w2m;
#pragma unroll
        for (int off = 8; off >= 1; off >>= 1)
            v += __shfl_xor_sync(FULLMASK, v, off, 16);
        if (lane == 0) out[seq_base + ss] = v + bias2;
    }
}

extern "C" void kernel_launch(void* const* d_in, const int* in_sizes, int n_in,
                              void* d_out, int out_size) {
    const float* x    = (const float*)d_in[0];
    const float* Wih0 = (const float*)d_in[1];
    const float* Whh0 = (const float*)d_in[2];
    const float* bih0 = (const float*)d_in[3];
    const float* bhh0 = (const float*)d_in[4];
    const float* Wih1 = (const float*)d_in[5];
    const float* Whh1 = (const float*)d_in[6];
    const float* bih1 = (const float*)d_in[7];
    const float* bhh1 = (const float*)d_in[8];
    const float* W1   = (const float*)d_in[9];
    const float* b1   = (const float*)d_in[10];
    const float* W2   = (const float*)d_in[11];
    const float* b2   = (const float*)d_in[12];
    float* out = (float*)d_out;

    int batch = in_sizes[0] / (T_LEN * IN_DIM);  // 4096

    cudaFuncSetAttribute(lstm_fused_kernel,
                         cudaFuncAttributeMaxDynamicSharedMemorySize,
                         (int)sizeof(SmemAll));

    int seqs_per_block = QUADS * SEQ_PER_QUAD;                       // 32
    int blocks = (batch + seqs_per_block - 1) / seqs_per_block;      // 128
    lstm_fused_kernel<<<blocks, THREADS, sizeof(SmemAll)>>>(
        x, Wih0, Whh0, bih0, bhh0, Wih1, Whh1, bih1, bhh1,
        W1, b1, W2, b2, out, batch);
}

// round 13
// speedup vs baseline: 1.6222x; 1.6222x over previous
#include <cuda_runtime.h>

// 2-layer LSTM (IN=16, H=32, T=512, B=4096) + MLP head, fully fused.
// R13 = R9 (layer-split warp pairs, S=8, one L0 + one L1 warp per SMSP,
// smem-staged seq-pair-packed activations, 1 named 64-thread bar/step)
// with HW tanh.approx.f32 activations:
//   tanh(x)    = tanh.approx (1 MUFU, lat ~16)
//   sigmoid(x) = 0.5*tanh(x/2)+0.5 (1 MUFU + 1 FMA)
// MUFU drops 80 -> 40 per warp-step (1280 -> 640 cyc/SMSP-step) and the
// serial cell-tail chain shortens ~2.5x. Validated in R12: rel_err 5.6e-6.

#define FULLMASK 0xffffffffu
typedef unsigned long long u64;

constexpr int T_LEN = 512;
constexpr int IN_DIM = 16;
constexpr int H_DIM = 32;
constexpr int SEQ_PER_PAIR = 8;
constexpr int PAIRS_PER_BLOCK = 4;
constexpr int THREADS = 256;          // warps 0-3 = L0 of pair w, 4-7 = L1
constexpr int HROW = 34;              // u64 row stride (272B, 16B-aligned)
constexpr int XROW = 18;              // u64 row stride (144B, 16B-aligned)

// Weights: [j][unit] float4 = (wi,wf,wg,wo).
struct SmemW {
    float4 wih0[IN_DIM][H_DIM];
    float4 whh0[H_DIM][H_DIM];
    float4 wih1[H_DIM][H_DIM];
    float4 whh1[H_DIM][H_DIM];
    float4 bg0[H_DIM];
    float4 bg1[H_DIM];
};

// Per-pair staging. Rows: [seq-pair sp][unit/dim as u64 = (val_s0, val_s1)]
struct __align__(16) Stage {
    u64 h0[2][4][HROW];   // double-buffered, written by L0, read by both
    u64 h1[2][4][HROW];   // L1-private
    u64 x[2][4][XROW];    // L0-private
};

struct SmemAll {
    SmemW w;
    Stage st[PAIRS_PER_BLOCK];
};

__device__ __forceinline__ u64 fma2(u64 a, u64 b, u64 c) {
    u64 d;
    asm("fma.rn.f32x2 %0, %1, %2, %3;" : "=l"(d) : "l"(a), "l"(b), "l"(c));
    return d;
}
__device__ __forceinline__ u64 pack2(float v) {
    u64 r;
    asm("mov.b64 %0, {%1, %1};" : "=l"(r) : "f"(v));
    return r;
}
__device__ __forceinline__ u64 pack2f(float a, float b) {
    u64 r;
    asm("mov.b64 %0, {%1, %2};" : "=l"(r) : "f"(a), "f"(b));
    return r;
}
__device__ __forceinline__ float2 unpack2(u64 v) {
    float2 r;
    asm("mov.b64 {%0, %1}, %2;" : "=f"(r.x), "=f"(r.y) : "l"(v));
    return r;
}

__device__ __forceinline__ float tanh_ap(float v) {
    float r;
    asm("tanh.approx.f32 %0, %1;" : "=f"(r) : "f"(v));
    return r;
}
__device__ __forceinline__ float sig_ap(float v) {
    return fmaf(tanh_ap(v * 0.5f), 0.5f, 0.5f);
}

__device__ __forceinline__ void pair_bar(int pair) {
    asm volatile("bar.sync %0, %1;" :: "r"(pair + 1), "r"(64) : "memory");
}

// One j-pair contribution: weight quads w0 (j=2jp), w1 (j=2jp+1); acts are
// seq-pair-packed u64. 8 FFMA2 per sp.
#define JP_STEP(W0, W1, ACTP)                                              \
    do {                                                                   \
        u64 wi0 = pack2((W0).x), wf0 = pack2((W0).y);                      \
        u64 wg0 = pack2((W0).z), wo0 = pack2((W0).w);                      \
        u64 wi1 = pack2((W1).x), wf1 = pack2((W1).y);                      \
        u64 wg1 = pack2((W1).z), wo1 = pack2((W1).w);                      \
        _Pragma("unroll")                                                  \
        for (int sp = 0; sp < 4; sp++) {                                   \
            ulonglong2 a = *reinterpret_cast<const ulonglong2*>(ACTP(sp)); \
            ai[sp] = fma2(wi0, a.x, ai[sp]);                               \
            af[sp] = fma2(wf0, a.x, af[sp]);                               \
            ag[sp] = fma2(wg0, a.x, ag[sp]);                               \
            ao[sp] = fma2(wo0, a.x, ao[sp]);                               \
            ai[sp] = fma2(wi1, a.y, ai[sp]);                               \
            af[sp] = fma2(wf1, a.y, af[sp]);                               \
            ag[sp] = fma2(wg1, a.y, ag[sp]);                               \
            ao[sp] = fma2(wo1, a.y, ao[sp]);                               \
        }                                                                  \
    } while (0)

__global__ void __launch_bounds__(THREADS, 1)
lstm_fused_kernel(const float* __restrict__ x,
                  const float* __restrict__ Wih0, const float* __restrict__ Whh0,
                  const float* __restrict__ bih0, const float* __restrict__ bhh0,
                  const float* __restrict__ Wih1, const float* __restrict__ Whh1,
                  const float* __restrict__ bih1, const float* __restrict__ bhh1,
                  const float* __restrict__ W1, const float* __restrict__ b1,
                  const float* __restrict__ W2, const float* __restrict__ b2,
                  float* __restrict__ out, int batch) {
    extern __shared__ char smem_raw[];
    SmemAll* sm = reinterpret_cast<SmemAll*>(smem_raw);
    SmemW* s = &sm->w;

    const int tid = threadIdx.x;

    // ---- Stage weights as [j][unit] gate quads ----
    for (int i = tid; i < IN_DIM * H_DIM; i += THREADS) {
        int j = i / H_DIM, u = i % H_DIM;
        s->wih0[j][u] = make_float4(Wih0[(0 * H_DIM + u) * IN_DIM + j],
                                    Wih0[(1 * H_DIM + u) * IN_DIM + j],
                                    Wih0[(2 * H_DIM + u) * IN_DIM + j],
                                    Wih0[(3 * H_DIM + u) * IN_DIM + j]);
    }
    for (int i = tid; i < H_DIM * H_DIM; i += THREADS) {
        int j = i / H_DIM, u = i % H_DIM;
        s->whh0[j][u] = make_float4(Whh0[(0 * H_DIM + u) * H_DIM + j],
                                    Whh0[(1 * H_DIM + u) * H_DIM + j],
                                    Whh0[(2 * H_DIM + u) * H_DIM + j],
                                    Whh0[(3 * H_DIM + u) * H_DIM + j]);
        s->wih1[j][u] = make_float4(Wih1[(0 * H_DIM + u) * H_DIM + j],
                                    Wih1[(1 * H_DIM + u) * H_DIM + j],
                                    Wih1[(2 * H_DIM + u) * H_DIM + j],
                                    Wih1[(3 * H_DIM + u) * H_DIM + j]);
        s->whh1[j][u] = make_float4(Whh1[(0 * H_DIM + u) * H_DIM + j],
                                    Whh1[(1 * H_DIM + u) * H_DIM + j],
                                    Whh1[(2 * H_DIM + u) * H_DIM + j],
                                    Whh1[(3 * H_DIM + u) * H_DIM + j]);
    }
    for (int u = tid; u < H_DIM; u += THREADS) {
        s->bg0[u] = make_float4(bih0[0 * H_DIM + u] + bhh0[0 * H_DIM + u],
                                bih0[1 * H_DIM + u] + bhh0[1 * H_DIM + u],
                                bih0[2 * H_DIM + u] + bhh0[2 * H_DIM + u],
                                bih0[3 * H_DIM + u] + bhh0[3 * H_DIM + u]);
        s->bg1[u] = make_float4(bih1[0 * H_DIM + u] + bhh1[0 * H_DIM + u],
                                bih1[1 * H_DIM + u] + bhh1[1 * H_DIM + u],
                                bih1[2 * H_DIM + u] + bhh1[2 * H_DIM + u],
                                bih1[3 * H_DIM + u] + bhh1[3 * H_DIM + u]);
    }

    const int warp = tid >> 5;
    const int lane = tid & 31;         // lane = hidden unit
    const int pair = warp & 3;
    const int role = warp >> 2;        // 0 = layer-0 warp, 1 = layer-1 warp
    Stage* st = &sm->st[pair];
    const int seq_base = (blockIdx.x * PAIRS_PER_BLOCK + pair) * SEQ_PER_PAIR;

    const int xs = lane >> 2;
    const int xq = lane & 3;
    const size_t seq_stride = (size_t)T_LEN * IN_DIM;
    const float* xload = x + (size_t)(seq_base + xs) * seq_stride + 4 * xq;

    // ---- Init staging ----
    if (seq_base < batch) {
        if (role == 0) {
#pragma unroll
            for (int sp = 0; sp < 4; sp++) st->h0[0][sp][lane] = 0ull;
            float4 v = *reinterpret_cast<const float4*>(xload);
            float* fr = reinterpret_cast<float*>(st->x[0][xs >> 1]);
            int half = xs & 1;
            fr[(4 * xq + 0) * 2 + half] = v.x;
            fr[(4 * xq + 1) * 2 + half] = v.y;
            fr[(4 * xq + 2) * 2 + half] = v.z;
            fr[(4 * xq + 3) * 2 + half] = v.w;
        } else {
#pragma unroll
            for (int sp = 0; sp < 4; sp++) st->h1[0][sp][lane] = 0ull;
        }
    }
    __syncthreads();
    if (seq_base >= batch) return;

    if (role == 0) {
        // ================= Layer-0 warp =================
        const float4 bv = s->bg0[lane];
        const u64 BI = pack2(bv.x), BF = pack2(bv.y);
        const u64 BG = pack2(bv.z), BO = pack2(bv.w);
        float c0[8] = {0, 0, 0, 0, 0, 0, 0, 0};

        for (int t = 0; t < T_LEN; t++) {
            const int buf = t & 1, nbuf = buf ^ 1;
            float4 xn = make_float4(0.f, 0.f, 0.f, 0.f);
            if (t + 1 < T_LEN)
                xn = *reinterpret_cast<const float4*>(xload + (t + 1) * IN_DIM);

            u64 ai[4], af[4], ag[4], ao[4];
#pragma unroll
            for (int sp = 0; sp < 4; sp++) {
                ai[sp] = BI; af[sp] = BF; ag[sp] = BG; ao[sp] = BO;
            }
#pragma unroll
            for (int jp = 0; jp < IN_DIM / 2; jp++) {
                float4 w0 = s->wih0[2 * jp][lane];
                float4 w1 = s->wih0[2 * jp + 1][lane];
#define ACT_X(sp) (&st->x[buf][sp][2 * jp])
                JP_STEP(w0, w1, ACT_X);
#undef ACT_X
            }
#pragma unroll
            for (int jp = 0; jp < H_DIM / 2; jp++) {
                float4 w0 = s->whh0[2 * jp][lane];
                float4 w1 = s->whh0[2 * jp + 1][lane];
#define ACT_H0(sp) (&st->h0[buf][sp][2 * jp])
                JP_STEP(w0, w1, ACT_H0);
#undef ACT_H0
            }
            // Cell 0 + stage h0(t)
#pragma unroll
            for (int sp = 0; sp < 4; sp++) {
                float2 vi = unpack2(ai[sp]), vf = unpack2(af[sp]);
                float2 vg = unpack2(ag[sp]), vo = unpack2(ao[sp]);
                float i0 = sig_ap(vi.x), i1 = sig_ap(vi.y);
                float f0 = sig_ap(vf.x), f1 = sig_ap(vf.y);
                float g0 = tanh_ap(vg.x), g1 = tanh_ap(vg.y);
                float o0 = sig_ap(vo.x), o1 = sig_ap(vo.y);
                c0[2 * sp]     = fmaf(f0, c0[2 * sp],     i0 * g0);
                c0[2 * sp + 1] = fmaf(f1, c0[2 * sp + 1], i1 * g1);
                st->h0[nbuf][sp][lane] =
                    pack2f(o0 * tanh_ap(c0[2 * sp]),
                           o1 * tanh_ap(c0[2 * sp + 1]));
            }
            // Stage x(t+1)
            {
                float* fr = reinterpret_cast<float*>(st->x[nbuf][xs >> 1]);
                int half = xs & 1;
                fr[(4 * xq + 0) * 2 + half] = xn.x;
                fr[(4 * xq + 1) * 2 + half] = xn.y;
                fr[(4 * xq + 2) * 2 + half] = xn.z;
                fr[(4 * xq + 3) * 2 + half] = xn.w;
            }
            pair_bar(pair);  // h0(t) + x(t+1) visible to the L1 warp
        }
        return;
    }

    // ================= Layer-1 warp =================
    const float4 bv = s->bg1[lane];
    const u64 BI = pack2(bv.x), BF = pack2(bv.y);
    const u64 BG = pack2(bv.z), BO = pack2(bv.w);
    float c1[8] = {0, 0, 0, 0, 0, 0, 0, 0};
    float h1n[8] = {0, 0, 0, 0, 0, 0, 0, 0};

    for (int t = 0; t < T_LEN; t++) {
        const int buf = t & 1, nbuf = buf ^ 1;

        u64 ai[4], af[4], ag[4], ao[4];
#pragma unroll
        for (int sp = 0; sp < 4; sp++) {
            ai[sp] = BI; af[sp] = BF; ag[sp] = BG; ao[sp] = BO;
        }
        // hh1 first: own h1(t-1); independent of L0's h0(t).
#pragma unroll
        for (int jp = 0; jp < H_DIM / 2; jp++) {
            float4 w0 = s->whh1[2 * jp][lane];
            float4 w1 = s->whh1[2 * jp + 1][lane];
#define ACT_H1(sp) (&st->h1[buf][sp][2 * jp])
            JP_STEP(w0, w1, ACT_H1);
#undef ACT_H1
        }
        pair_bar(pair);  // wait for L0's h0(t) in h0[nbuf]
#pragma unroll
        for (int jp = 0; jp < H_DIM / 2; jp++) {
            float4 w0 = s->wih1[2 * jp][lane];
            float4 w1 = s->wih1[2 * jp + 1][lane];
#define ACT_H0N(sp) (&st->h0[nbuf][sp][2 * jp])
            JP_STEP(w0, w1, ACT_H0N);
#undef ACT_H0N
        }
        // Cell 1 + stage h1(t)
#pragma unroll
        for (int sp = 0; sp < 4; sp++) {
            float2 vi = unpack2(ai[sp]), vf = unpack2(af[sp]);
            float2 vg = unpack2(ag[sp]), vo = unpack2(ao[sp]);
            float i0 = sig_ap(vi.x), i1 = sig_ap(vi.y);
            float f0 = sig_ap(vf.x), f1 = sig_ap(vf.y);
            float g0 = tanh_ap(vg.x), g1 = tanh_ap(vg.y);
            float o0 = sig_ap(vo.x), o1 = sig_ap(vo.y);
            c1[2 * sp]     = fmaf(f0, c1[2 * sp],     i0 * g0);
            c1[2 * sp + 1] = fmaf(f1, c1[2 * sp + 1], i1 * g1);
            h1n[2 * sp]     = o0 * tanh_ap(c1[2 * sp]);
            h1n[2 * sp + 1] = o1 * tanh_ap(c1[2 * sp + 1]);
            st->h1[nbuf][sp][lane] = pack2f(h1n[2 * sp], h1n[2 * sp + 1]);
        }
        __syncwarp();  // order h1 stores vs next iteration's cross-lane reads
    }

    // ---- Head (L1 warp): z = relu(h1 @ W1.T + b1); y = z @ W2.T + b2 ----
    float bias2 = __ldg(b2);
    float bm = (lane < 16) ? __ldg(b1 + lane) : 0.f;
    float w2m = (lane < 16) ? __ldg(W2 + lane) : 0.f;
    float z[8];
#pragma unroll
    for (int ss = 0; ss < 8; ss++) z[ss] = bm;
#pragma unroll
    for (int j = 0; j < H_DIM; j++) {
        float wm = (lane < 16) ? __ldg(W1 + lane * H_DIM + j) : 0.f;
#pragma unroll
        for (int ss = 0; ss < 8; ss++) {
            float hj = __shfl_sync(FULLMASK, h1n[ss], j);
            z[ss] = fmaf(wm, hj, z[ss]);
        }
    }
#pragma unroll
    for (int ss = 0; ss < 8; ss++) {
        float v = fmaxf(z[ss], 0.f) * w2m;
#pragma unroll
        for (int off = 8; off >= 1; off >>= 1)
            v += __shfl_xor_sync(FULLMASK, v, off, 16);
        if (lane == 0) out[seq_base + ss] = v + bias2;
    }
}

extern "C" void kernel_launch(void* const* d_in, const int* in_sizes, int n_in,
                              void* d_out, int out_size) {
    const float* x    = (const float*)d_in[0];
    const float* Wih0 = (const float*)d_in[1];
    const float* Whh0 = (const float*)d_in[2];
    const float* bih0 = (const float*)d_in[3];
    const float* bhh0 = (const float*)d_in[4];
    const float* Wih1 = (const float*)d_in[5];
    const float* Whh1 = (const float*)d_in[6];
    const float* bih1 = (const float*)d_in[7];
    const float* bhh1 = (const float*)d_in[8];
    const float* W1   = (const float*)d_in[9];
    const float* b1   = (const float*)d_in[10];
    const float* W2   = (const float*)d_in[11];
    const float* b2   = (const float*)d_in[12];
    float* out = (float*)d_out;

    int batch = in_sizes[0] / (T_LEN * IN_DIM);  // 4096

    cudaFuncSetAttribute(lstm_fused_kernel,
                         cudaFuncAttributeMaxDynamicSharedMemorySize,
                         (int)sizeof(SmemAll));

    int pairs = (batch + SEQ_PER_PAIR - 1) / SEQ_PER_PAIR;          // 512
    int blocks = (pairs + PAIRS_PER_BLOCK - 1) / PAIRS_PER_BLOCK;   // 128
    lstm_fused_kernel<<<blocks, THREADS, sizeof(SmemAll)>>>(
        x, Wih0, Whh0, bih0, bhh0, Wih1, Whh1, bih1, bhh1,
        W1, b1, W2, b2, out, batch);
}